// round 16
// baseline (speedup 1.0000x reference)
#include <cuda_runtime.h>

// GRAPE: 20 commuting X-rotations (shared Pauli-X generator) collapse to ONE
// rotation: Theta = sum(a_k)*DT/2, U = cos(Theta) I - i sin(Theta) X.
// 4 fused FMAs per column -> pure 256 MiB stream at the GB300 mixed-R/W
// HBM roofline (~6.2 TB/s effective incl. cross-replay L2 write-drain).
//
// FINAL config (measured optimum family, 43.5us):
//   - contiguous pair-split: grid halves own independent 2-read/2-write
//     stream pairs
//   - ILP=1, float4, 256-thread blocks
//   - fully streaming cache policy: __ldcs loads + __stcs stores (inputs
//     have no intra-replay reuse and thrash L2 across replays; outputs are
//     write-once — skip L2 allocate churn on both sides)
// Proven neutral/worse across 14 rounds: ILP=2, 256-bit LDG/STG, L2
// evict-priority hints, stream interleave, persistent grid, block size
// in {128, 512, 1024}. Traffic (256 MiB/replay) is irreducible.
//
//   pair A: (r0, m1) -> out0r = c*r0 + s*m1 ; out1i = c*m1 - s*r0
//   pair B: (r1, m0) -> out1r = c*r1 + s*m0 ; out0i = c*m0 - s*r1

#define NUM_STEPS 20
#define DT_HALF   (0.5f * (1.0f / 20.0f))
#define BATCH     8388608

__global__ __launch_bounds__(256) void grape_kernel(
    const float* __restrict__ amps,
    const float* __restrict__ sr,
    const float* __restrict__ si,
    float* __restrict__ out)
{
    float theta = 0.0f;
#pragma unroll
    for (int k = 0; k < NUM_STEPS; k++) theta += __ldg(&amps[k]);
    theta *= DT_HALF;
    const float c = cosf(theta);
    const float s = sinf(theta);

    const int n4  = BATCH / 4;                 // 2,097,152 float4 per row
    const int tid = blockIdx.x * blockDim.x + threadIdx.x;

    if (tid < n4) {
        // ---- pair A: (r0, m1) -> out0r, out1i ----
        const int i = tid;
        const float4* sr0 = (const float4*)sr;
        const float4* si1 = (const float4*)(si + (size_t)BATCH);
        float4* out0r = (float4*)out;
        float4* out1i = (float4*)(out + 3 * (size_t)BATCH);

        float4 a = __ldcs(&sr0[i]);   // r0
        float4 b = __ldcs(&si1[i]);   // m1

        float4 o1, o2;
        o1.x = fmaf(c, a.x,  s * b.x);  o2.x = fmaf(c, b.x, -s * a.x);
        o1.y = fmaf(c, a.y,  s * b.y);  o2.y = fmaf(c, b.y, -s * a.y);
        o1.z = fmaf(c, a.z,  s * b.z);  o2.z = fmaf(c, b.z, -s * a.z);
        o1.w = fmaf(c, a.w,  s * b.w);  o2.w = fmaf(c, b.w, -s * a.w);

        __stcs(&out0r[i], o1);
        __stcs(&out1i[i], o2);
    } else {
        // ---- pair B: (r1, m0) -> out1r, out0i ----
        const int i = tid - n4;
        const float4* sr1 = (const float4*)(sr + (size_t)BATCH);
        const float4* si0 = (const float4*)si;
        float4* out1r = (float4*)(out + (size_t)BATCH);
        float4* out0i = (float4*)(out + 2 * (size_t)BATCH);

        float4 a = __ldcs(&sr1[i]);   // r1
        float4 b = __ldcs(&si0[i]);   // m0

        float4 o1, o2;
        o1.x = fmaf(c, a.x,  s * b.x);  o2.x = fmaf(c, b.x, -s * a.x);
        o1.y = fmaf(c, a.y,  s * b.y);  o2.y = fmaf(c, b.y, -s * a.y);
        o1.z = fmaf(c, a.z,  s * b.z);  o2.z = fmaf(c, b.z, -s * a.z);
        o1.w = fmaf(c, a.w,  s * b.w);  o2.w = fmaf(c, b.w, -s * a.w);

        __stcs(&out1r[i], o1);
        __stcs(&out0i[i], o2);
    }
}

extern "C" void kernel_launch(void* const* d_in, const int* in_sizes, int n_in,
                              void* d_out, int out_size)
{
    const float* amps = (const float*)d_in[0];  // [20]
    const float* sr   = (const float*)d_in[1];  // [2, B]
    const float* si   = (const float*)d_in[2];  // [2, B]
    float* out        = (float*)d_out;          // [2, 2, B]

    const int n4 = BATCH / 4;
    const int threads = 256;
    const int blocks = (2 * n4) / threads;      // 16384
    grape_kernel<<<blocks, threads>>>(amps, sr, si, out);
}